// round 11
// baseline (speedup 1.0000x reference)
#include <cuda_runtime.h>
#include <cstdint>
#include <math.h>

#define B_ 1024
#define H_ 512
#define D_ 256
#define T_ 10
#define P_ 64

// ---------------- scratch (device globals; no allocs) ----------------
__device__ float g_pool1[B_*196*64];    // NHWC (B,14,14,64), tf32-rounded
__device__ float g_conv2[B_*196*128];   // NHWC (B,14,14,128), tf32-rounded
__device__ float g_pool2[B_*36*128];    // NHWC (B,6,6,128), tf32-rounded
__device__ float g_conv3[B_*16*128];    // NHWC (B,4,4,128), tf32-rounded
__device__ float g_conv4[B_*4*256];     // NHWC (B,2,2,256) pre-pool, tf32-rounded
__device__ float g_emb[B_*256];         // pooled emb, tf32-rounded
__device__ float g_embproj[B_*2048];    // (B,4H) fp32
__device__ float g_h[B_*H_];            // tf32-rounded
__device__ float g_c[B_*H_];            // fp32
__device__ float g_gates[B_*2048];      // fp32
__device__ float g_wT[66*2048];         // w_ih[:,0:66]^T (fp32, epilogue adds)
__device__ float g_w2t[128*576];        // cw2 reordered (oc, kyx, ic), tf32
__device__ float g_w3t[128*1152];       // cw3 reordered, tf32
__device__ float g_w4t[256*1152];       // cw4 reordered, tf32
__device__ float g_wih2[2048*256];      // w_ih[:,66:] packed, tf32
__device__ float g_whh[2048*512];       // w_hh, tf32

// ---------------- helpers ----------------
__device__ __forceinline__ float to_tf32(float x) {
    unsigned int y;
    asm("cvt.rna.tf32.f32 %0, %1;" : "=r"(y) : "f"(x));
    return __uint_as_float(y);
}

__device__ __forceinline__ void mma8(float4& d, float2 a_r0, float2 a_r1, float2 b) {
    asm volatile(
        "mma.sync.aligned.m16n8k8.row.col.f32.tf32.tf32.f32 "
        "{%0,%1,%2,%3}, {%4,%5,%6,%7}, {%8,%9}, {%0,%1,%2,%3};\n"
        : "+f"(d.x), "+f"(d.y), "+f"(d.z), "+f"(d.w)
        : "r"(__float_as_uint(a_r0.x)), "r"(__float_as_uint(a_r1.x)),
          "r"(__float_as_uint(a_r0.y)), "r"(__float_as_uint(a_r1.y)),
          "r"(__float_as_uint(b.x)),   "r"(__float_as_uint(b.y)));
}

__device__ __forceinline__ void cp16(uint32_t dst, const void* src, bool v) {
    int sz = v ? 16 : 0;
    asm volatile("cp.async.cg.shared.global [%0], [%1], 16, %2;\n"
                 :: "r"(dst), "l"(src), "r"(sz));
}

// ---------------- init: zero c and out ----------------
__global__ void init_kernel(float* __restrict__ out) {
    int idx = blockIdx.x*256 + threadIdx.x;
    if (idx < B_*H_) g_c[idx] = 0.f;
    if (idx < B_)    out[idx] = 0.f;
}

// ---------------- weight prep: reorder + tf32-round ----------------
__global__ void prep_kernel(const float* __restrict__ cw2,
                            const float* __restrict__ cw3,
                            const float* __restrict__ cw4,
                            const float* __restrict__ w_ih,
                            const float* __restrict__ w_hh) {
    int i = blockIdx.x*256 + threadIdx.x;
    if (i < 73728) {
        int oc = i/576, k = i%576, kyx = k >> 6, ic = k & 63;
        g_w2t[i] = to_tf32(cw2[oc*576 + ic*9 + kyx]);
    } else if (i < 221184) {
        int j = i - 73728;
        int oc = j/1152, k = j%1152, kyx = k >> 7, ic = k & 127;
        g_w3t[j] = to_tf32(cw3[oc*1152 + ic*9 + kyx]);
    } else if (i < 516096) {
        int j = i - 221184;
        int oc = j/1152, k = j%1152, kyx = k >> 7, ic = k & 127;
        g_w4t[j] = to_tf32(cw4[oc*1152 + ic*9 + kyx]);
    } else if (i < 1040384) {
        int j = i - 516096;
        int n = j >> 8, k = j & 255;
        g_wih2[j] = to_tf32(w_ih[n*322 + 66 + k]);
    } else if (i < 2088960) {
        int j = i - 1040384;
        int n = j >> 9, k = j & 511;
        g_whh[j] = to_tf32(w_hh[n*512 + k]);
    } else if (i < 2224128) {
        int j = i - 2088960;
        int c = j >> 11, n = j & 2047;
        g_wT[j] = w_ih[n*322 + c];
    }
}

// ---------------- conv1 + relu + pool3s2 -> g_pool1 (direct pooling) --------
// 28KB static smem; each warp handles 4 oc per half; conv recomputed per pool tap.
__global__ void conv1_kernel(const float* __restrict__ obs,
                             const float* __restrict__ w,
                             const float* __restrict__ bias) {
    __shared__ float img[784];
    __shared__ float pbuf[32*196];
    int b = blockIdx.x;
    int tid = threadIdx.x;
    int warp = tid >> 5, lane = tid & 31;
    for (int i = tid; i < 784; i += 256) img[i] = obs[b*784 + i];
    __syncthreads();
    for (int half = 0; half < 2; half++) {
        #pragma unroll
        for (int ocl = 0; ocl < 4; ocl++) {
            int oc32 = warp*4 + ocl;
            int oc = half*32 + oc32;
            float wv[9];
            #pragma unroll
            for (int j = 0; j < 9; j++) wv[j] = w[oc*9 + j];
            float bv = bias[oc];
            for (int idx = lane; idx < 196; idx += 32) {
                int py = idx/14, px = idx%14;
                float m = 0.f;
                #pragma unroll
                for (int dy = 0; dy < 3; dy++) {
                    #pragma unroll
                    for (int dx = 0; dx < 3; dx++) {
                        int oy = 2*py + dy, ox = 2*px + dx;
                        float acc = bv;
                        #pragma unroll
                        for (int ky = 0; ky < 3; ky++) {
                            int iy = oy + ky - 2;
                            if (iy < 0 || iy >= 28) continue;
                            #pragma unroll
                            for (int kx = 0; kx < 3; kx++) {
                                int ix = ox + kx - 2;
                                if (ix < 0 || ix >= 28) continue;
                                acc += img[iy*28 + ix] * wv[ky*3 + kx];
                            }
                        }
                        m = fmaxf(m, fmaxf(acc, 0.f));
                    }
                }
                pbuf[oc32*196 + idx] = to_tf32(m);
            }
        }
        __syncthreads();
        for (int i = tid; i < 32*196; i += 256) {
            int p = i >> 5, oc32 = i & 31;
            g_pool1[(b*196 + p)*64 + half*32 + oc32] = pbuf[oc32*196 + p];
        }
        __syncthreads();
    }
}

// ---------------- GEMM stage issue (forceinline, no closure) ----------------
// Weight buffers are selected INSIDE device code (never passed from host).
template<int MODE>
__device__ __forceinline__ const float* weightB() {
    if constexpr (MODE == 0) return g_wih2;
    else if constexpr (MODE == 1) return g_w2t;
    else if constexpr (MODE == 2) return g_w3t;
    else if constexpr (MODE == 3) return g_w4t;
    else return g_whh;
}

template<int MODE>
__device__ __forceinline__ void issue_stage(
        int it2, int nIter, int bb, int yy, int xx,
        const float* __restrict__ bptr, int c0,
        uint32_t aDst0, uint32_t aDst1, uint32_t bDst0, uint32_t bDst1) {
    if (it2 < nIter) {
        const int k0 = it2 << 4;
        const uint32_t so = (uint32_t)(it2 % 3) * 8192u;
        const float* sa; bool va = true;
        if constexpr (MODE == 0)      sa = g_emb + bb*256 + k0;
        else if constexpr (MODE == 4) sa = g_h   + bb*512 + k0;
        else if constexpr (MODE == 1) {
            int kyx = k0 >> 6, ky = kyx/3, kx = kyx - ky*3;
            int iy = yy + ky - 1, ix = xx + kx - 1;
            va = ((unsigned)iy < 14u) && ((unsigned)ix < 14u);
            int iyc = va ? iy : 0, ixc = va ? ix : 0;
            sa = g_pool1 + (bb*196 + iyc*14 + ixc)*64 + (k0 & 63);
        } else if constexpr (MODE == 2) {
            int kyx = k0 >> 7, ky = kyx/3, kx = kyx - ky*3;
            sa = g_pool2 + (bb*36 + (yy+ky)*6 + (xx+kx))*128 + (k0 & 127);
        } else {
            int kyx = k0 >> 7, ky = kyx/3, kx = kyx - ky*3;
            sa = g_conv3 + (bb*16 + (yy+ky)*4 + (xx+kx))*128 + (k0 & 127);
        }
        cp16(aDst0 + so, sa + c0*4,     va);
        cp16(aDst1 + so, sa + c0*4 + 4, va);
        const float* sb = bptr + k0;
        cp16(bDst0 + so, sb + c0*4,     true);
        cp16(bDst1 + so, sb + c0*4 + 4, true);
    }
    asm volatile("cp.async.commit_group;\n");
}

// ---------------- tf32 tensor-core GEMM, 128x128x16, cp.async 3-stage -------
// MODE 0: embproj = g_emb @ g_wih2^T + b_ih + b_hh
// MODE 1: conv2 implicit gemm (g_pool1, g_w2t), relu+round -> g_conv2
// MODE 2: conv3 implicit gemm (g_pool2, g_w3t), relu+round -> g_conv3
// MODE 3: conv4 implicit gemm (g_conv3, g_w4t), relu+round -> g_conv4
// MODE 4: gates = g_h @ g_whh^T + embproj + wT[id] + wT[64+oo]
template<int MODE>
__global__ void __launch_bounds__(256) gemm_kernel(
        const float* __restrict__ bias,
        const float* __restrict__ bias2,
        const int* __restrict__ ids,
        const int* __restrict__ oos,
        int K, int t) {
    __shared__ __align__(16) float As[3][2048];   // [stage][128 rows x 16 k], swizzled
    __shared__ __align__(16) float Bs[3][2048];
    const int tid = threadIdx.x;
    const int m0 = blockIdx.x * 128;
    const int n0 = blockIdx.y * 128;

    // ---- staging: each thread owns 1 A row + 1 B row, two 16B chunks ----
    const int rowS = tid >> 1;
    const int c0 = (tid & 1) * 2;
    int bb = 0, yy = 0, xx = 0;
    {
        int m = m0 + rowS;
        if constexpr (MODE == 1) { bb = m/196; int p = m - bb*196; yy = p/14; xx = p - yy*14; }
        else if constexpr (MODE == 2) { bb = m >> 4; int p = m & 15; yy = p >> 2; xx = p & 3; }
        else if constexpr (MODE == 3) { bb = m >> 2; int p = m & 3;  yy = p >> 1; xx = p & 1; }
        else { bb = m; }
    }
    constexpr int LDB = (MODE == 0) ? 256 : (MODE == 4) ? 512 : (MODE == 1) ? 576 : 1152;
    const float* bptr = weightB<MODE>() + (size_t)(n0 + rowS) * LDB;

    const int xs = rowS & 3;
    uint32_t aBase = (uint32_t)__cvta_generic_to_shared(&As[0][0]);
    uint32_t bBase = (uint32_t)__cvta_generic_to_shared(&Bs[0][0]);
    const uint32_t aDst0 = aBase + (rowS*16 + ((c0    ) ^ xs)*4) * 4;
    const uint32_t aDst1 = aBase + (rowS*16 + ((c0 + 1) ^ xs)*4) * 4;
    const uint32_t bDst0 = bBase + (rowS*16 + ((c0    ) ^ xs)*4) * 4;
    const uint32_t bDst1 = bBase + (rowS*16 + ((c0 + 1) ^ xs)*4) * 4;

    const int nIter = K >> 4;

    // ---- compute assignment ----
    const int lane = tid & 31, warp = tid >> 5;
    const int wm = (warp & 3)*32, wn = (warp >> 2)*64;
    const int r = lane >> 2, kc2 = (lane & 3)*2;
    const int xr = r & 3;
    const int kq0 = ((((kc2 >> 2)    ) ^ xr) << 2) + (kc2 & 3);
    const int kq1 = ((((kc2 >> 2) + 2) ^ xr) << 2) + (kc2 & 3);

    float4 acc[2][8];
    #pragma unroll
    for (int mi = 0; mi < 2; mi++)
        #pragma unroll
        for (int j = 0; j < 8; j++) acc[mi][j] = make_float4(0.f, 0.f, 0.f, 0.f);

    issue_stage<MODE>(0, nIter, bb, yy, xx, bptr, c0, aDst0, aDst1, bDst0, bDst1);
    issue_stage<MODE>(1, nIter, bb, yy, xx, bptr, c0, aDst0, aDst1, bDst0, bDst1);

    for (int it = 0; it < nIter; it++) {
        asm volatile("cp.async.wait_group 1;\n");
        __syncthreads();
        issue_stage<MODE>(it + 2, nIter, bb, yy, xx, bptr, c0, aDst0, aDst1, bDst0, bDst1);
        const float* A  = As[it % 3];
        const float* Bt = Bs[it % 3];
        #pragma unroll
        for (int s = 0; s < 2; s++) {
            const int kq = s ? kq1 : kq0;
            float2 a00 = *(const float2*)(A + ((wm + r     ) << 4) + kq);
            float2 a01 = *(const float2*)(A + ((wm + r +  8) << 4) + kq);
            float2 a10 = *(const float2*)(A + ((wm + r + 16) << 4) + kq);
            float2 a11 = *(const float2*)(A + ((wm + r + 24) << 4) + kq);
            #pragma unroll
            for (int j = 0; j < 8; j++) {
                float2 bf = *(const float2*)(Bt + ((wn + j*8 + r) << 4) + kq);
                mma8(acc[0][j], a00, a01, bf);
                mma8(acc[1][j], a10, a11, bf);
            }
        }
        __syncthreads();
    }

    // ---- epilogue: thread owns rows {wm+r+16mi, +8}, cols {wn+j*8+kc2, +1} ----
    if constexpr (MODE == 4) {
        #pragma unroll
        for (int mi = 0; mi < 2; mi++) {
            int row0 = m0 + wm + mi*16 + r;
            int row1 = row0 + 8;
            int id0 = ids[row0*10 + t - 1], oo0 = oos[row0*10 + t - 1];
            int id1 = ids[row1*10 + t - 1], oo1 = oos[row1*10 + t - 1];
            #pragma unroll
            for (int j = 0; j < 8; j++) {
                int col = n0 + wn + j*8 + kc2;
                float4 d = acc[mi][j];
                float2 e0 = *(const float2*)&g_embproj[row0*2048 + col];
                float2 wa0 = *(const float2*)&g_wT[id0*2048 + col];
                float2 wb0 = *(const float2*)&g_wT[(64 + oo0)*2048 + col];
                *(float2*)&g_gates[row0*2048 + col] =
                    make_float2(d.x + e0.x + wa0.x + wb0.x, d.y + e0.y + wa0.y + wb0.y);
                float2 e1 = *(const float2*)&g_embproj[row1*2048 + col];
                float2 wa1 = *(const float2*)&g_wT[id1*2048 + col];
                float2 wb1 = *(const float2*)&g_wT[(64 + oo1)*2048 + col];
                *(float2*)&g_gates[row1*2048 + col] =
                    make_float2(d.z + e1.x + wa1.x + wb1.x, d.w + e1.y + wa1.y + wb1.y);
            }
        }
    } else {
        #pragma unroll
        for (int mi = 0; mi < 2; mi++) {
            int row0 = m0 + wm + mi*16 + r;
            int row1 = row0 + 8;
            #pragma unroll
            for (int j = 0; j < 8; j++) {
                int col = n0 + wn + j*8 + kc2;
                float b0, b1;
                if constexpr (MODE == 0) { b0 = bias[col] + bias2[col]; b1 = bias[col+1] + bias2[col+1]; }
                else                     { b0 = bias[col];              b1 = bias[col+1]; }
                float4 d = acc[mi][j];
                if constexpr (MODE == 0) {
                    *(float2*)&g_embproj[row0*2048 + col] = make_float2(d.x + b0, d.y + b1);
                    *(float2*)&g_embproj[row1*2048 + col] = make_float2(d.z + b0, d.w + b1);
                } else if constexpr (MODE == 1) {
                    *(float2*)&g_conv2[row0*128 + col] =
                        make_float2(to_tf32(fmaxf(d.x + b0, 0.f)), to_tf32(fmaxf(d.y + b1, 0.f)));
                    *(float2*)&g_conv2[row1*128 + col] =
                        make_float2(to_tf32(fmaxf(d.z + b0, 0.f)), to_tf32(fmaxf(d.w + b1, 0.f)));
                } else if constexpr (MODE == 2) {
                    *(float2*)&g_conv3[row0*128 + col] =
                        make_float2(to_tf32(fmaxf(d.x + b0, 0.f)), to_tf32(fmaxf(d.y + b1, 0.f)));
                    *(float2*)&g_conv3[row1*128 + col] =
                        make_float2(to_tf32(fmaxf(d.z + b0, 0.f)), to_tf32(fmaxf(d.w + b1, 0.f)));
                } else {
                    *(float2*)&g_conv4[row0*256 + col] =
                        make_float2(to_tf32(fmaxf(d.x + b0, 0.f)), to_tf32(fmaxf(d.y + b1, 0.f)));
                    *(float2*)&g_conv4[row1*256 + col] =
                        make_float2(to_tf32(fmaxf(d.z + b0, 0.f)), to_tf32(fmaxf(d.w + b1, 0.f)));
                }
            }
        }
    }
}

// ---------------- pool after conv2: (B,14,14,128) -> (B,6,6,128) ----------------
__global__ void pool2_kernel() {
    int idx = blockIdx.x*256 + threadIdx.x;
    if (idx >= B_*36*128) return;
    int c = idx & 127;
    int r = idx >> 7;
    int p = r % 36; int b = r / 36;
    int py = p / 6, px = p % 6;
    float m = 0.f;
    #pragma unroll
    for (int dy = 0; dy < 3; dy++)
        #pragma unroll
        for (int dx = 0; dx < 3; dx++)
            m = fmaxf(m, g_conv2[(b*196 + (2*py+dy)*14 + 2*px+dx)*128 + c]);
    g_pool2[idx] = m;
}

// ---------------- pool after conv4: (B,2,2,256) -> (B,256) ----------------
__global__ void pool4_kernel() {
    int idx = blockIdx.x*256 + threadIdx.x;
    if (idx >= B_*256) return;
    int c = idx & 255;
    int b = idx >> 8;
    const float* p = g_conv4 + b*1024 + c;
    g_emb[idx] = fmaxf(fmaxf(p[0], p[256]), fmaxf(p[512], p[768]));
}

// ---------------- LSTM cell elementwise ----------------
__global__ void cell_kernel(int use_gates) {
    int idx = blockIdx.x*256 + threadIdx.x;
    if (idx >= B_*H_) return;
    const float* gates = use_gates ? g_gates : g_embproj;
    int b = idx >> 9;
    int j = idx & 511;
    const float* g = gates + b*2048;
    float ig = g[j], fg = g[j+512], gg = g[j+1024], og = g[j+1536];
    float cp = g_c[idx];
    float si = 1.f/(1.f + expf(-ig));
    float sf = 1.f/(1.f + expf(-fg));
    float so = 1.f/(1.f + expf(-og));
    float cc = sf*cp + si*tanhf(gg);
    g_c[idx] = cc;
    g_h[idx] = to_tf32(so*tanhf(cc));
}

// ---------------- logits + log-softmax + gather + accumulate ----------------
__global__ void logits_kernel(const float* __restrict__ lin_w,
                              const float* __restrict__ lin_b,
                              const int* __restrict__ ids,
                              const int* __restrict__ oos,
                              float* __restrict__ out, int t) {
    __shared__ float hsh[512];
    __shared__ float lg[66];
    int b = blockIdx.x, tid = threadIdx.x;
    for (int i = tid; i < 512; i += 128) hsh[i] = g_h[b*512 + i];
    __syncthreads();
    if (tid < 66) {
        float acc = lin_b[tid];
        const float* wr = lin_w + tid*512;
        #pragma unroll 8
        for (int k = 0; k < 512; k++) acc += hsh[k]*wr[k];
        lg[tid] = acc;
    }
    __syncthreads();
    if (tid < 32) {
        float v0 = lg[tid], v1 = lg[tid+32];
        float mx = fmaxf(v0, v1);
        #pragma unroll
        for (int o = 16; o > 0; o >>= 1) mx = fmaxf(mx, __shfl_xor_sync(0xffffffffu, mx, o));
        float s = expf(v0 - mx) + expf(v1 - mx);
        #pragma unroll
        for (int o = 16; o > 0; o >>= 1) s += __shfl_xor_sync(0xffffffffu, s, o);
        if (tid == 0) {
            int idt = ids[b*10 + t];
            int oot = oos[b*10 + t];
            float lp_id = lg[idt] - mx - logf(s);
            float a0 = lg[64], a1 = lg[65];
            float mo = fmaxf(a0, a1);
            float ls = mo + logf(expf(a0 - mo) + expf(a1 - mo));
            float lp_oo = (oot ? a1 : a0) - ls;
            out[b] += lp_id + (t > 0 ? lp_oo : 0.f);
        }
    }
}

// ---------------- launch ----------------
extern "C" void kernel_launch(void* const* d_in, const int* in_sizes, int n_in,
                              void* d_out, int out_size) {
    const float* obs  = (const float*)d_in[0];
    const int*   ids  = (const int*)  d_in[1];
    const int*   oos  = (const int*)  d_in[2];
    const float* cw1  = (const float*)d_in[3];
    const float* cb1  = (const float*)d_in[4];
    const float* cw2  = (const float*)d_in[5];
    const float* cb2  = (const float*)d_in[6];
    const float* cw3  = (const float*)d_in[7];
    const float* cb3  = (const float*)d_in[8];
    const float* cw4  = (const float*)d_in[9];
    const float* cb4  = (const float*)d_in[10];
    const float* w_ih = (const float*)d_in[11];
    const float* w_hh = (const float*)d_in[12];
    const float* b_ih = (const float*)d_in[13];
    const float* b_hh = (const float*)d_in[14];
    const float* lin_w= (const float*)d_in[15];
    const float* lin_b= (const float*)d_in[16];
    float* out = (float*)d_out;

    init_kernel<<<(B_*H_ + 255)/256, 256>>>(out);
    prep_kernel<<<(2224128 + 255)/256, 256>>>(cw2, cw3, cw4, w_ih, w_hh);
    conv1_kernel<<<B_, 256>>>(obs, cw1, cb1);
    // conv2: M=200704, N=128, K=576
    gemm_kernel<1><<<dim3(1568, 1), 256>>>(cb2, nullptr, nullptr, nullptr, 576, 0);
    pool2_kernel<<<(B_*36*128 + 255)/256, 256>>>();
    // conv3: M=16384, N=128, K=1152
    gemm_kernel<2><<<dim3(128, 1), 256>>>(cb3, nullptr, nullptr, nullptr, 1152, 0);
    // conv4 (pre-pool): M=4096, N=256, K=1152
    gemm_kernel<3><<<dim3(32, 2), 256>>>(cb4, nullptr, nullptr, nullptr, 1152, 0);
    pool4_kernel<<<(B_*256 + 255)/256, 256>>>();
    // embproj: M=1024, N=2048, K=256
    gemm_kernel<0><<<dim3(8, 16), 256>>>(b_ih, b_hh, nullptr, nullptr, 256, 0);
    // step 0: gates == embproj (h = 0)
    cell_kernel<<<(B_*H_ + 255)/256, 256>>>(0);
    logits_kernel<<<B_, 128>>>(lin_w, lin_b, ids, oos, out, 0);
    // steps 1..9
    for (int t = 1; t < T_; t++) {
        gemm_kernel<4><<<dim3(8, 16), 256>>>(nullptr, nullptr, ids, oos, 512, t);
        cell_kernel<<<(B_*H_ + 255)/256, 256>>>(1);
        logits_kernel<<<B_, 128>>>(lin_w, lin_b, ids, oos, out, t);
    }
}

// round 12
// speedup vs baseline: 1.1513x; 1.1513x over previous
#include <cuda_runtime.h>
#include <cuda_bf16.h>
#include <cstdint>
#include <math.h>

#define B_ 1024
#define H_ 512
#define T_ 10

typedef __nv_bfloat16 bf16;

__device__ bf16  g_pool1[B_*196*64];
__device__ bf16  g_conv2[B_*196*128];
__device__ bf16  g_pool2[B_*36*128];
__device__ bf16  g_conv3[B_*16*128];
__device__ bf16  g_conv4[B_*4*256];
__device__ bf16  g_emb[B_*256];
__device__ float g_embproj[B_*2048];
__device__ bf16  g_h[B_*H_];
__device__ float g_c[B_*H_];
__device__ float g_gates[B_*2048];
__device__ float g_wT[66*2048];
__device__ bf16  g_w2t[128*576];
__device__ bf16  g_w3t[128*1152];
__device__ bf16  g_w4t[256*1152];
__device__ bf16  g_wih2[2048*256];
__device__ bf16  g_whh[2048*512];

__device__ __forceinline__ void mma16(float4& d, uint32_t a0, uint32_t a1,
        uint32_t a2, uint32_t a3, uint32_t b0, uint32_t b1) {
    asm volatile(
        "mma.sync.aligned.m16n8k16.row.col.f32.bf16.bf16.f32 "
        "{%0,%1,%2,%3}, {%4,%5,%6,%7}, {%8,%9}, {%0,%1,%2,%3};\n"
        : "+f"(d.x), "+f"(d.y), "+f"(d.z), "+f"(d.w)
        : "r"(a0), "r"(a1), "r"(a2), "r"(a3), "r"(b0), "r"(b1));
}
__device__ __forceinline__ void ldsm4(uint32_t& r0, uint32_t& r1,
        uint32_t& r2, uint32_t& r3, uint32_t addr) {
    asm volatile("ldmatrix.sync.aligned.m8n8.x4.shared.b16 {%0,%1,%2,%3}, [%4];"
                 : "=r"(r0), "=r"(r1), "=r"(r2), "=r"(r3) : "r"(addr));
}
__device__ __forceinline__ void cp16(uint32_t dst, const void* src, bool v) {
    int sz = v ? 16 : 0;
    asm volatile("cp.async.cg.shared.global [%0], [%1], 16, %2;\n"
                 :: "r"(dst), "l"(src), "r"(sz));
}

__global__ void init_kernel(float* __restrict__ out) {
    int idx = blockIdx.x*256 + threadIdx.x;
    if (idx < B_*H_) g_c[idx] = 0.f;
    if (idx < B_)    out[idx] = 0.f;
}

__global__ void prep_kernel(const float* __restrict__ cw2,
                            const float* __restrict__ cw3,
                            const float* __restrict__ cw4,
                            const float* __restrict__ w_ih,
                            const float* __restrict__ w_hh) {
    int i = blockIdx.x*256 + threadIdx.x;
    if (i < 73728) {
        int oc = i/576, k = i%576, kyx = k >> 6, ic = k & 63;
        g_w2t[i] = __float2bfloat16_rn(cw2[oc*576 + ic*9 + kyx]);
    } else if (i < 221184) {
        int j = i - 73728;
        int oc = j/1152, k = j%1152, kyx = k >> 7, ic = k & 127;
        g_w3t[j] = __float2bfloat16_rn(cw3[oc*1152 + ic*9 + kyx]);
    } else if (i < 516096) {
        int j = i - 221184;
        int oc = j/1152, k = j%1152, kyx = k >> 7, ic = k & 127;
        g_w4t[j] = __float2bfloat16_rn(cw4[oc*1152 + ic*9 + kyx]);
    } else if (i < 1040384) {
        int j = i - 516096;
        g_wih2[j] = __float2bfloat16_rn(w_ih[(j >> 8)*322 + 66 + (j & 255)]);
    } else if (i < 2088960) {
        int j = i - 1040384;
        g_whh[j] = __float2bfloat16_rn(w_hh[(j >> 9)*512 + (j & 511)]);
    } else if (i < 2224128) {
        int j = i - 2088960;
        g_wT[j] = w_ih[(j & 2047)*322 + (j >> 11)];
    }
}

__global__ void conv1_kernel(const float* __restrict__ obs,
                             const float* __restrict__ w,
                             const float* __restrict__ bias) {
    __shared__ float img[784];
    __shared__ float pbuf[32*196];
    int b = blockIdx.x, tid = threadIdx.x;
    int warp = tid >> 5, lane = tid & 31;
    for (int i = tid; i < 784; i += 256) img[i] = obs[b*784 + i];
    __syncthreads();
    for (int half = 0; half < 2; half++) {
        #pragma unroll
        for (int ocl = 0; ocl < 4; ocl++) {
            int oc32 = warp*4 + ocl, oc = half*32 + oc32;
            float wv[9];
            #pragma unroll
            for (int j = 0; j < 9; j++) wv[j] = w[oc*9 + j];
            float bv = bias[oc];
            for (int idx = lane; idx < 196; idx += 32) {
                int py = idx/14, px = idx%14;
                float m = 0.f;
                #pragma unroll
                for (int dy = 0; dy < 3; dy++)
                    #pragma unroll
                    for (int dx = 0; dx < 3; dx++) {
                        int oy = 2*py + dy, ox = 2*px + dx;
                        float acc = bv;
                        #pragma unroll
                        for (int ky = 0; ky < 3; ky++) {
                            int iy = oy + ky - 2;
                            if (iy < 0 || iy >= 28) continue;
                            #pragma unroll
                            for (int kx = 0; kx < 3; kx++) {
                                int ix = ox + kx - 2;
                                if (ix < 0 || ix >= 28) continue;
                                acc += img[iy*28 + ix] * wv[ky*3 + kx];
                            }
                        }
                        m = fmaxf(m, fmaxf(acc, 0.f));
                    }
                pbuf[oc32*196 + idx] = m;
            }
        }
        __syncthreads();
        for (int i = tid; i < 32*196; i += 256) {
            int p = i >> 5, oc32 = i & 31;
            g_pool1[(b*196 + p)*64 + half*32 + oc32] = __float2bfloat16_rn(pbuf[oc32*196 + p]);
        }
        __syncthreads();
    }
}

// ---- bf16 GEMM 128x128x64, ldmatrix + m16n8k16, 3-stage cp.async ----
#define STG 18432
#define GEMM_SMEM (6*STG)

template<int MODE>
__device__ __forceinline__ const bf16* weightB() {
    if constexpr (MODE == 0) return g_wih2;
    else if constexpr (MODE == 1) return g_w2t;
    else if constexpr (MODE == 2) return g_w3t;
    else if constexpr (MODE == 3) return g_w4t;
    else return g_whh;
}

template<int MODE>
__device__ __forceinline__ void issue_stage(
        int it2, int nIter, int bb, int yy, int xx,
        const bf16* __restrict__ bptr, int gb, uint32_t aDst, uint32_t bDst) {
    if (it2 < nIter) {
        uint32_t so = (uint32_t)(it2 % 3) * STG;
        const bf16* sa; bool va = true;
        if constexpr (MODE == 0)      sa = g_emb + bb*256 + it2*64;
        else if constexpr (MODE == 4) sa = g_h   + bb*512 + it2*64;
        else if constexpr (MODE == 1) {
            int ky = it2/3, kx = it2 - ky*3;
            int iy = yy + ky - 1, ix = xx + kx - 1;
            va = ((unsigned)iy < 14u) && ((unsigned)ix < 14u);
            int iyc = va ? iy : 0, ixc = va ? ix : 0;
            sa = g_pool1 + (bb*196 + iyc*14 + ixc)*64;
        } else if constexpr (MODE == 2) {
            int kyx = it2 >> 1; int ky = kyx/3, kx = kyx - ky*3;
            sa = g_pool2 + (bb*36 + (yy+ky)*6 + (xx+kx))*128 + (it2&1)*64;
        } else {
            int kyx = it2 >> 1; int ky = kyx/3, kx = kyx - ky*3;
            sa = g_conv3 + (bb*16 + (yy+ky)*4 + (xx+kx))*128 + (it2&1)*64;
        }
        const bf16* sb = bptr + it2*64;
        sa += gb*8; sb += gb*8;
        #pragma unroll
        for (int g = 0; g < 4; g++) {
            cp16(aDst + so + g*16, sa + g*8, va);
            cp16(bDst + so + g*16, sb + g*8, true);
        }
    }
    asm volatile("cp.async.commit_group;\n");
}

template<int MODE>
__global__ void __launch_bounds__(256) gemm_kernel(
        const float* __restrict__ bias,
        const float* __restrict__ bias2,
        const int* __restrict__ ids,
        const int* __restrict__ oos,
        int K, int t) {
    extern __shared__ __align__(16) char dsm[];
    uint32_t smBase = (uint32_t)__cvta_generic_to_shared(dsm);
    const int tid = threadIdx.x;
    const int m0 = blockIdx.x * 128;
    const int n0 = blockIdx.y * 128;

    const int rowS = tid >> 1;
    const int gb = (tid & 1) * 4;
    int bb = 0, yy = 0, xx = 0;
    {
        int m = m0 + rowS;
        if constexpr (MODE == 1) { bb = m/196; int p = m - bb*196; yy = p/14; xx = p - yy*14; }
        else if constexpr (MODE == 2) { bb = m >> 4; int p = m & 15; yy = p >> 2; xx = p & 3; }
        else if constexpr (MODE == 3) { bb = m >> 2; int p = m & 3;  yy = p >> 1; xx = p & 1; }
        else { bb = m; }
    }
    constexpr int LDK = (MODE == 0) ? 256 : (MODE == 4) ? 512 : (MODE == 1) ? 576 : 1152;
    const bf16* bptr = weightB<MODE>() + (size_t)(n0 + rowS) * LDK;
    const uint32_t aDst = smBase + rowS*144 + gb*16;
    const uint32_t bDst = smBase + 3*STG + rowS*144 + gb*16;

    const int nIter = K >> 6;

    const int lane = tid & 31, warp = tid >> 5;
    const int wm = (warp & 3)*32, wn = (warp >> 2)*64;
    const int r = lane >> 2, kc2 = (lane & 3)*2;
    const int lrow = (lane & 7) + ((lane >> 3) & 1)*8;
    const int lgA  = (lane >> 4) & 1;
    const uint32_t offA0 = (uint32_t)((wm + lrow)*144 + lgA*16);
    const uint32_t offA1 = offA0 + 16*144;
    const int q = lane >> 3;
    const int brow = (lane & 7) + (q >> 1)*8;
    const int bgl  = q & 1;
    uint32_t offB[4];
    #pragma unroll
    for (int jp = 0; jp < 4; jp++)
        offB[jp] = (uint32_t)((wn + jp*16 + brow)*144 + bgl*16);

    float4 acc[2][8];
    #pragma unroll
    for (int mi = 0; mi < 2; mi++)
        #pragma unroll
        for (int j = 0; j < 8; j++) acc[mi][j] = make_float4(0.f, 0.f, 0.f, 0.f);

    issue_stage<MODE>(0, nIter, bb, yy, xx, bptr, gb, aDst, bDst);
    issue_stage<MODE>(1, nIter, bb, yy, xx, bptr, gb, aDst, bDst);

    int st = 0;
    for (int it = 0; it < nIter; it++) {
        asm volatile("cp.async.wait_group 1;\n");
        __syncthreads();
        issue_stage<MODE>(it + 2, nIter, bb, yy, xx, bptr, gb, aDst, bDst);
        uint32_t sA = smBase + (uint32_t)st*STG;
        uint32_t sB = sA + 3*STG;
        #pragma unroll
        for (int s = 0; s < 4; s++) {
            uint32_t a00, a01, a02, a03, a10, a11, a12, a13;
            ldsm4(a00, a01, a02, a03, sA + offA0 + s*32);
            ldsm4(a10, a11, a12, a13, sA + offA1 + s*32);
            #pragma unroll
            for (int jp = 0; jp < 4; jp++) {
                uint32_t b0, b1, b2, b3;
                ldsm4(b0, b1, b2, b3, sB + offB[jp] + s*32);
                mma16(acc[0][2*jp  ], a00, a01, a02, a03, b0, b1);
                mma16(acc[0][2*jp+1], a00, a01, a02, a03, b2, b3);
                mma16(acc[1][2*jp  ], a10, a11, a12, a13, b0, b1);
                mma16(acc[1][2*jp+1], a10, a11, a12, a13, b2, b3);
            }
        }
        st = (st == 2) ? 0 : st + 1;
    }

    if constexpr (MODE == 4) {
        #pragma unroll
        for (int mi = 0; mi < 2; mi++) {
            int row0 = m0 + wm + mi*16 + r, row1 = row0 + 8;
            int id0 = ids[row0*10 + t - 1], oo0 = oos[row0*10 + t - 1];
            int id1 = ids[row1*10 + t - 1], oo1 = oos[row1*10 + t - 1];
            #pragma unroll
            for (int j = 0; j < 8; j++) {
                int col = n0 + wn + j*8 + kc2;
                float4 d = acc[mi][j];
                float2 e0 = *(const float2*)&g_embproj[row0*2048 + col];
                float2 wa0 = *(const float2*)&g_wT[id0*2048 + col];
                float2 wb0 = *(const float2*)&g_wT[(64 + oo0)*2048 + col];
                *(float2*)&g_gates[row0*2048 + col] =
                    make_float2(d.x + e0.x + wa0.x + wb0.x, d.y + e0.y + wa0.y + wb0.y);
                float2 e1 = *(const float2*)&g_embproj[row1*2048 + col];
                float2 wa1 = *(const float2*)&g_wT[id1*2048 + col];
                float2 wb1 = *(const float2*)&g_wT[(64 + oo1)*2048 + col];
                *(float2*)&g_gates[row1*2048 + col] =
                    make_float2(d.z + e1.x + wa1.x + wb1.x, d.w + e1.y + wa1.y + wb1.y);
            }
        }
    } else if constexpr (MODE == 0) {
        #pragma unroll
        for (int mi = 0; mi < 2; mi++) {
            int row0 = m0 + wm + mi*16 + r, row1 = row0 + 8;
            #pragma unroll
            for (int j = 0; j < 8; j++) {
                int col = n0 + wn + j*8 + kc2;
                float b0 = bias[col] + bias2[col], b1 = bias[col+1] + bias2[col+1];
                float4 d = acc[mi][j];
                *(float2*)&g_embproj[row0*2048 + col] = make_float2(d.x + b0, d.y + b1);
                *(float2*)&g_embproj[row1*2048 + col] = make_float2(d.z + b0, d.w + b1);
            }
        }
    } else {
        constexpr int LDO = (MODE == 3) ? 256 : 128;
        bf16* outp = (MODE == 1) ? g_conv2 : (MODE == 2) ? g_conv3 : g_conv4;
        #pragma unroll
        for (int mi = 0; mi < 2; mi++) {
            int row0 = m0 + wm + mi*16 + r, row1 = row0 + 8;
            #pragma unroll
            for (int j = 0; j < 8; j++) {
                int col = n0 + wn + j*8 + kc2;
                float b0 = bias[col], b1 = bias[col+1];
                float4 d = acc[mi][j];
                __nv_bfloat162 v0, v1;
                v0.x = __float2bfloat16_rn(fmaxf(d.x + b0, 0.f));
                v0.y = __float2bfloat16_rn(fmaxf(d.y + b1, 0.f));
                v1.x = __float2bfloat16_rn(fmaxf(d.z + b0, 0.f));
                v1.y = __float2bfloat16_rn(fmaxf(d.w + b1, 0.f));
                *(__nv_bfloat162*)&outp[row0*LDO + col] = v0;
                *(__nv_bfloat162*)&outp[row1*LDO + col] = v1;
            }
        }
    }
}

__global__ void pool2_kernel() {
    int idx = blockIdx.x*256 + threadIdx.x;
    if (idx >= B_*36*128) return;
    int c = idx & 127, rr = idx >> 7;
    int p = rr % 36, b = rr / 36;
    int py = p / 6, px = p % 6;
    float m = 0.f;
    #pragma unroll
    for (int dy = 0; dy < 3; dy++)
        #pragma unroll
        for (int dx = 0; dx < 3; dx++)
            m = fmaxf(m, __bfloat162float(g_conv2[(b*196 + (2*py+dy)*14 + 2*px+dx)*128 + c]));
    g_pool2[idx] = __float2bfloat16_rn(m);
}

__global__ void pool4_kernel() {
    int idx = blockIdx.x*256 + threadIdx.x;
    if (idx >= B_*256) return;
    int c = idx & 255, b = idx >> 8;
    const bf16* p = g_conv4 + b*1024 + c;
    float m = fmaxf(fmaxf(__bfloat162float(p[0]), __bfloat162float(p[256])),
                    fmaxf(__bfloat162float(p[512]), __bfloat162float(p[768])));
    g_emb[idx] = __float2bfloat16_rn(m);
}

__global__ void cell_kernel(int use_gates) {
    int idx = blockIdx.x*256 + threadIdx.x;
    if (idx >= B_*H_) return;
    const float* gates = use_gates ? g_gates : g_embproj;
    int b = idx >> 9, j = idx & 511;
    const float* g = gates + b*2048;
    float ig = g[j], fg = g[j+512], gg = g[j+1024], og = g[j+1536];
    float cp = g_c[idx];
    float si = 1.f/(1.f + expf(-ig));
    float sf = 1.f/(1.f + expf(-fg));
    float so = 1.f/(1.f + expf(-og));
    float cc = sf*cp + si*tanhf(gg);
    g_c[idx] = cc;
    g_h[idx] = __float2bfloat16_rn(so*tanhf(cc));
}

__global__ void logits_kernel(const float* __restrict__ lin_w,
                              const float* __restrict__ lin_b,
                              const int* __restrict__ ids,
                              const int* __restrict__ oos,
                              float* __restrict__ out, int t) {
    __shared__ float hsh[512];
    __shared__ float lg[66];
    int b = blockIdx.x, tid = threadIdx.x;
    for (int i = tid; i < 512; i += 128) hsh[i] = __bfloat162float(g_h[b*512 + i]);
    __syncthreads();
    if (tid < 66) {
        float acc = lin_b[tid];
        const float* wr = lin_w + tid*512;
        #pragma unroll 8
        for (int k = 0; k < 512; k++) acc += hsh[k]*wr[k];
        lg[tid] = acc;
    }
    __syncthreads();
    if (tid < 32) {
        float v0 = lg[tid], v1 = lg[tid+32];
        float mx = fmaxf(v0, v1);
        #pragma unroll
        for (int o = 16; o > 0; o >>= 1) mx = fmaxf(mx, __shfl_xor_sync(0xffffffffu, mx, o));
        float s = expf(v0 - mx) + expf(v1 - mx);
        #pragma unroll
        for (int o = 16; o > 0; o >>= 1) s += __shfl_xor_sync(0xffffffffu, s, o);
        if (tid == 0) {
            int idt = ids[b*10 + t], oot = oos[b*10 + t];
            float lp_id = lg[idt] - mx - logf(s);
            float a0 = lg[64], a1 = lg[65];
            float mo = fmaxf(a0, a1);
            float ls = mo + logf(expf(a0 - mo) + expf(a1 - mo));
            float lp_oo = (oot ? a1 : a0) - ls;
            out[b] += lp_id + (t > 0 ? lp_oo : 0.f);
        }
    }
}

extern "C" void kernel_launch(void* const* d_in, const int* in_sizes, int n_in,
                              void* d_out, int out_size) {
    const float* obs  = (const float*)d_in[0];
    const int*   ids  = (const int*)  d_in[1];
    const int*   oos  = (const int*)  d_in[2];
    const float* cw1  = (const float*)d_in[3];
    const float* cb1  = (const float*)d_in[4];
    const float* cw2  = (const float*)d_in[5];
    const float* cb2  = (const float*)d_in[6];
    const float* cw3  = (const float*)d_in[7];
    const float* cb3  = (const float*)d_in[8];
    const float* cw4  = (const float*)d_in[9];
    const float* cb4  = (const float*)d_in[10];
    const float* w_ih = (const float*)d_in[11];
    const float* w_hh = (const float*)d_in[12];
    const float* b_ih = (const float*)d_in[13];
    const float* b_hh = (const float*)d_in[14];
    const float* lin_w= (const float*)d_in[15];
    const float* lin_b= (const float*)d_in[16];
    float* out = (float*)d_out;

    cudaFuncSetAttribute(gemm_kernel<0>, cudaFuncAttributeMaxDynamicSharedMemorySize, GEMM_SMEM);
    cudaFuncSetAttribute(gemm_kernel<1>, cudaFuncAttributeMaxDynamicSharedMemorySize, GEMM_SMEM);
    cudaFuncSetAttribute(gemm_kernel<2>, cudaFuncAttributeMaxDynamicSharedMemorySize, GEMM_SMEM);
    cudaFuncSetAttribute(gemm_kernel<3>, cudaFuncAttributeMaxDynamicSharedMemorySize, GEMM_SMEM);
    cudaFuncSetAttribute(gemm_kernel<4>, cudaFuncAttributeMaxDynamicSharedMemorySize, GEMM_SMEM);

    init_kernel<<<(B_*H_ + 255)/256, 256>>>(out);
    prep_kernel<<<(2224128 + 255)/256, 256>>>(cw2, cw3, cw4, w_ih, w_hh);
    conv1_kernel<<<B_, 256>>>(obs, cw1, cb1);
    gemm_kernel<1><<<dim3(1568, 1), 256, GEMM_SMEM>>>(cb2, nullptr, nullptr, nullptr, 576, 0);
    pool2_kernel<<<(B_*36*128 + 255)/256, 256>>>();
    gemm_kernel<2><<<dim3(128, 1), 256, GEMM_SMEM>>>(cb3, nullptr, nullptr, nullptr, 1152, 0);
    gemm_kernel<3><<<dim3(32, 2), 256, GEMM_SMEM>>>(cb4, nullptr, nullptr, nullptr, 1152, 0);
    pool4_kernel<<<(B_*256 + 255)/256, 256>>>();
    gemm_kernel<0><<<dim3(8, 16), 256, GEMM_SMEM>>>(b_ih, b_hh, nullptr, nullptr, 256, 0);
    cell_kernel<<<(B_*H_ + 255)/256, 256>>>(0);
    logits_kernel<<<B_, 128>>>(lin_w, lin_b, ids, oos, out, 0);
    for (int t = 1; t < T_; t++) {
        gemm_kernel<4><<<dim3(8, 16), 256, GEMM_SMEM>>>(nullptr, nullptr, ids, oos, 512, t);
        cell_kernel<<<(B_*H_ + 255)/256, 256>>>(1);
        logits_kernel<<<B_, 128>>>(lin_w, lin_b, ids, oos, out, t);
    }
}